// round 15
// baseline (speedup 1.0000x reference)
#include <cuda_runtime.h>
#include <cuda_fp16.h>
#include <math.h>
#include <stdint.h>

// ---------------- problem constants ----------------
#define B_SZ   8192
#define OUT_SZ 1024
#define IN_SZ  1024
#define D_SZ   4
#define NSTEPS 8
#define NROW   (B_SZ * D_SZ)          /* 32768 state rows n = b*4+d */
#define MTOT_I (OUT_SZ * D_SZ)        /* 4096 init-GEMM M */
#define EPS_N  1e-12f

// ---------------- tiling ----------------
#define BTM  128                      /* CTA tile M */
#define BTN  256                      /* CTA tile N */
#define KCH  64                       /* k per chunk */
#define NCHUNK 16                     /* K = 1024 */
#define NTHR 256                      /* 8 warps: 2 (m) x 4 (n), warp tile 64x64 */
#define STAGES 2
// stage layout: Ah 16KB | Al 16KB | Bh 32KB | Bl 32KB = 96KB
#define A_LO_OFF 16384
#define B_OFF    32768
#define B_SUB    32768
#define STG_BYTES 98304
#define DSMEM (STAGES * STG_BYTES + 1024)

#define SWZ(o) ((o) ^ (((o) >> 3) & 0x70))

// ---------------- device buffers (split fp16) ----------------
__device__ __half g_Kth[OUT_SZ * OUT_SZ];               // tanh(coupling)+I, [i][j]
__device__ __half g_Ktl[OUT_SZ * OUT_SZ];
__device__ __half g_Wth[(size_t)MTOT_I * IN_SZ];        // W transposed [m=(o,d)][k]
__device__ __half g_Wtl[(size_t)MTOT_I * IN_SZ];
__device__ __half g_xh[(size_t)B_SZ * IN_SZ];           // x [b][k]
__device__ __half g_xl[(size_t)B_SZ * IN_SZ];
__device__ __half g_Vh[2][(size_t)NROW * OUT_SZ];       // state [n][j]
__device__ __half g_Vl[2][(size_t)NROW * OUT_SZ];

// ---------------- PTX helpers (baseline, sm_80-era) ----------------
__device__ __forceinline__ uint32_t smem_u32(const void* p) {
    uint32_t a;
    asm("{ .reg .u64 t; cvta.to.shared.u64 t, %1; cvt.u32.u64 %0, t; }" : "=r"(a) : "l"(p));
    return a;
}
__device__ __forceinline__ void cpasync16(uint32_t dst, const void* src) {
    asm volatile("cp.async.cg.shared.global [%0], [%1], 16;" :: "r"(dst), "l"(src));
}
#define CP_COMMIT() asm volatile("cp.async.commit_group;" ::: "memory")
#define CP_WAIT1()  asm volatile("cp.async.wait_group 1;" ::: "memory")

__device__ __forceinline__ void ldsm4(uint32_t* r, uint32_t addr) {
    asm volatile("ldmatrix.sync.aligned.m8n8.x4.shared.b16 {%0,%1,%2,%3}, [%4];"
                 : "=r"(r[0]), "=r"(r[1]), "=r"(r[2]), "=r"(r[3]) : "r"(addr));
}
__device__ __forceinline__ void mma16816(float* d, const uint32_t* a, const uint32_t* b) {
    asm volatile(
        "mma.sync.aligned.m16n8k16.row.col.f32.f16.f16.f32 "
        "{%0,%1,%2,%3}, {%4,%5,%6,%7}, {%8,%9}, {%0,%1,%2,%3};"
        : "+f"(d[0]), "+f"(d[1]), "+f"(d[2]), "+f"(d[3])
        : "r"(a[0]), "r"(a[1]), "r"(a[2]), "r"(a[3]), "r"(b[0]), "r"(b[1]));
}

// ---------------------------------------------------------------------------
// Prep kernels: build split-fp16 operands.
// ---------------------------------------------------------------------------
__global__ void prep_kt(const float* __restrict__ coup) {
    int idx = blockIdx.x * 256 + threadIdx.x;
    int i = idx >> 10, j = idx & 1023;
    float t = tanhf(coup[idx]) + (i == j ? 1.0f : 0.0f);
    __half h = __float2half(t);
    g_Kth[idx] = h;
    g_Ktl[idx] = __float2half(t - __half2float(h));
}

__global__ void prep_x(const float* __restrict__ x) {
    size_t idx = (size_t)blockIdx.x * 256 + threadIdx.x;
    float v = x[idx];
    __half h = __float2half(v);
    g_xh[idx] = h;
    g_xl[idx] = __float2half(v - __half2float(h));
}

// W[k][m] (1024 x 4096 row-major) -> Wt[m][k] split
__global__ void prep_wt(const float* __restrict__ W) {
    __shared__ float t[32][33];
    int tx = threadIdx.x & 31, ty = threadIdx.x >> 5;   // ty 0..7
    int m0 = blockIdx.x * 32, k0 = blockIdx.y * 32;
#pragma unroll
    for (int i = 0; i < 32; i += 8)
        t[ty + i][tx] = W[(size_t)(k0 + ty + i) * MTOT_I + m0 + tx];
    __syncthreads();
#pragma unroll
    for (int i = 0; i < 32; i += 8) {
        float v = t[tx][ty + i];
        __half h = __float2half(v);
        size_t off = (size_t)(m0 + ty + i) * IN_SZ + k0 + tx;
        g_Wth[off] = h;
        g_Wtl[off] = __float2half(v - __half2float(h));
    }
}

// ---------------------------------------------------------------------------
// Fused split-fp16 GEMM + normalize epilogue.
// C[m][n] = sum_k A[m][k]*B[n][k]  (3-pass split accumulate, fp32)
// Warp tile 64x64 (mi=0..3), 8 warps: wm in {0,1}, wn in {0..3}.
// MODE 0: init   A=Wt[m=(o,d)][k], B=x[b][k];  write V0[(b*4+d)][o] (norm over m-quads)
// MODE 1: step   A=Vt[n][j],       B=K'[i][j]; write Vout[n][i]     (norm over n-quads)
// MODE 2: step final -> write d_out[b][i][d] fp32
// ---------------------------------------------------------------------------
template <int MODE>
__global__ __launch_bounds__(NTHR, 1)
void gemm_f16(int sIn, const float* __restrict__ omega, float* __restrict__ out) {
    extern __shared__ char dsm_raw[];
    char* dsm = (char*)(((uintptr_t)dsm_raw + 1023) & ~(uintptr_t)1023);
    const uint32_t smemBase = smem_u32(dsm);

    const __half* __restrict__ Ah;
    const __half* __restrict__ Al;
    const __half* __restrict__ Bh;
    const __half* __restrict__ Bl;
    __half* __restrict__ Voh;
    __half* __restrict__ Vol;
    if (MODE == 0) {
        Ah = g_Wth; Al = g_Wtl; Bh = g_xh; Bl = g_xl;
        Voh = g_Vh[0]; Vol = g_Vl[0];
    } else {
        Ah = g_Vh[sIn]; Al = g_Vl[sIn]; Bh = g_Kth; Bl = g_Ktl;
        Voh = g_Vh[sIn ^ 1]; Vol = g_Vl[sIn ^ 1];
    }

    const int tid = threadIdx.x;
    const int lane = tid & 31;
    const int w = tid >> 5;
    const int wm = w >> 2;       // 2 m-warps of 64 rows
    const int wn = w & 3;        // 4 n-warps of 64 cols
    const int m0 = blockIdx.y * BTM;
    const int n0 = blockIdx.x * BTN;

    // ldmatrix per-thread UNSWIZZLED base offsets; swizzle applied per access.
    uint32_t aBase[4], bBase[4];
#pragma unroll
    for (int mi = 0; mi < 4; mi++) {
        int r = wm * 64 + mi * 16 + (lane & 7) + ((lane >> 3) & 1) * 8;
        int cc = (lane >> 4);
        aBase[mi] = (uint32_t)(r * 128 + cc * 16);
    }
#pragma unroll
    for (int nj = 0; nj < 4; nj++) {
        int r = wn * 64 + nj * 16 + (lane & 7) + ((lane >> 4) << 3);
        int cc = (lane >> 3) & 1;
        bBase[nj] = (uint32_t)(r * 128 + cc * 16);
    }

    float acc[4][8][4];
#pragma unroll
    for (int a = 0; a < 4; a++)
#pragma unroll
        for (int b = 0; b < 8; b++)
#pragma unroll
            for (int c = 0; c < 4; c++) acc[a][b][c] = 0.f;

    // chunk copy (KCH=64): sub-tiles Ah|Al (16KB each), Bh|Bl (32KB each).
    auto copy_chunk = [&](int stage, int k0) {
        const uint32_t sb = smemBase + (uint32_t)(stage * STG_BYTES);
        // A: 2048 16B-units (hi then lo), 8 per thread
#pragma unroll
        for (int i = 0; i < 8; i++) {
            int u = tid + i * NTHR;
            int sub = u >> 10;                 // 0 = hi, 1 = lo
            int r = (u & 1023) >> 3, cc = u & 7;
            const __half* src = (sub ? Al : Ah) +
                (size_t)(m0 + r) * 1024 + k0 + cc * 8;
            cpasync16(sb + sub * A_LO_OFF + SWZ((uint32_t)(r * 128 + cc * 16)), src);
        }
        // B: 4096 16B-units (hi then lo), 16 per thread
#pragma unroll
        for (int i = 0; i < 16; i++) {
            int u = tid + i * NTHR;
            int sub = u >> 11;
            int r = (u & 2047) >> 3, cc = u & 7;
            const __half* src = (sub ? Bl : Bh) +
                (size_t)(n0 + r) * 1024 + k0 + cc * 8;
            cpasync16(sb + B_OFF + sub * B_SUB + SWZ((uint32_t)(r * 128 + cc * 16)), src);
        }
    };

    copy_chunk(0, 0);  CP_COMMIT();
    copy_chunk(1, KCH); CP_COMMIT();

    for (int c = 0; c < NCHUNK; c++) {
        CP_WAIT1();
        __syncthreads();
        const uint32_t stg = smemBase + (uint32_t)((c & 1) * STG_BYTES);

#pragma unroll
        for (int s = 0; s < 4; s++) {
            const uint32_t ks = (uint32_t)(s * 32);
            // A fragments for all 4 mi (8 ldsm)
            uint32_t ah[4][4], al[4][4];
#pragma unroll
            for (int mi = 0; mi < 4; mi++) {
                ldsm4(ah[mi], stg + SWZ(aBase[mi] + ks));
                ldsm4(al[mi], stg + A_LO_OFF + SWZ(aBase[mi] + ks));
            }
            // nj pairs: B live set = 16 regs, acc reuse distance = 16 MMAs
#pragma unroll
            for (int njp = 0; njp < 4; njp += 2) {
                uint32_t bh[2][4], bl[2][4];
#pragma unroll
                for (int q = 0; q < 2; q++) {
                    ldsm4(bh[q], stg + B_OFF + SWZ(bBase[njp + q] + ks));
                    ldsm4(bl[q], stg + B_OFF + B_SUB + SWZ(bBase[njp + q] + ks));
                }
                // pass 1: ah * bh
#pragma unroll
                for (int q = 0; q < 2; q++)
#pragma unroll
                    for (int mi = 0; mi < 4; mi++) {
                        mma16816(acc[mi][2 * (njp + q) + 0], ah[mi], &bh[q][0]);
                        mma16816(acc[mi][2 * (njp + q) + 1], ah[mi], &bh[q][2]);
                    }
                // pass 2: ah * bl
#pragma unroll
                for (int q = 0; q < 2; q++)
#pragma unroll
                    for (int mi = 0; mi < 4; mi++) {
                        mma16816(acc[mi][2 * (njp + q) + 0], ah[mi], &bl[q][0]);
                        mma16816(acc[mi][2 * (njp + q) + 1], ah[mi], &bl[q][2]);
                    }
                // pass 3: al * bh
#pragma unroll
                for (int q = 0; q < 2; q++)
#pragma unroll
                    for (int mi = 0; mi < 4; mi++) {
                        mma16816(acc[mi][2 * (njp + q) + 0], al[mi], &bh[q][0]);
                        mma16816(acc[mi][2 * (njp + q) + 1], al[mi], &bh[q][2]);
                    }
            }
        }

        if (c + 2 < NCHUNK) {
            __syncthreads();               // all reads of this stage done
            copy_chunk(c & 1, (c + 2) * KCH);
        }
        CP_COMMIT();
    }

    // ---------------- epilogue ----------------
    if (MODE == 0) {
        // rows m=(o,d), cols b. Normalize over m-quads: lanes {l, l^4, l^8}.
#pragma unroll
        for (int mi = 0; mi < 4; mi++) {
            const int mrow = m0 + wm * 64 + mi * 16 + (lane >> 2);
#pragma unroll
            for (int fi = 0; fi < 8; fi++) {
                const int bcol = n0 + wn * 64 + fi * 8 + (lane & 3) * 2;
#pragma unroll
                for (int h = 0; h < 2; h++) {
                    const int m = mrow + h * 8;
                    const int o = m >> 2, d = m & 3;
                    float v0 = acc[mi][fi][h * 2 + 0];
                    float v1 = acc[mi][fi][h * 2 + 1];
                    float s0 = v0 * v0, s1 = v1 * v1;
                    s0 += __shfl_xor_sync(~0u, s0, 4); s0 += __shfl_xor_sync(~0u, s0, 8);
                    s1 += __shfl_xor_sync(~0u, s1, 4); s1 += __shfl_xor_sync(~0u, s1, 8);
                    v0 *= 1.f / fmaxf(sqrtf(s0), EPS_N);
                    v1 *= 1.f / fmaxf(sqrtf(s1), EPS_N);
                    size_t p0 = (size_t)(bcol * 4 + d) * 1024 + o;
                    size_t p1 = (size_t)((bcol + 1) * 4 + d) * 1024 + o;
                    __half h0 = __float2half(v0), h1 = __float2half(v1);
                    Voh[p0] = h0; Vol[p0] = __float2half(v0 - __half2float(h0));
                    Voh[p1] = h1; Vol[p1] = __float2half(v1 - __half2float(h1));
                }
            }
        }
    } else {
        // rows n=(b,d), cols i. Normalize over n-quads: lanes {l, l^4, l^8}.
#pragma unroll
        for (int mi = 0; mi < 4; mi++) {
            const int nrow = m0 + wm * 64 + mi * 16 + (lane >> 2);
            const int d = nrow & 3;
#pragma unroll
            for (int fi = 0; fi < 8; fi++) {
                const int icol = n0 + wn * 64 + fi * 8 + (lane & 3) * 2;
                const float om0 = omega[icol * 4 + d];
                const float om1 = omega[icol * 4 + 4 + d];
#pragma unroll
                for (int h = 0; h < 2; h++) {
                    const int n = nrow + h * 8;
                    float v0 = acc[mi][fi][h * 2 + 0] + om0;
                    float v1 = acc[mi][fi][h * 2 + 1] + om1;
                    float s0 = v0 * v0, s1 = v1 * v1;
                    s0 += __shfl_xor_sync(~0u, s0, 4); s0 += __shfl_xor_sync(~0u, s0, 8);
                    s1 += __shfl_xor_sync(~0u, s1, 4); s1 += __shfl_xor_sync(~0u, s1, 8);
                    v0 *= 1.f / fmaxf(sqrtf(s0), EPS_N);
                    v1 *= 1.f / fmaxf(sqrtf(s1), EPS_N);
                    if (MODE == 2) {
                        out[(size_t)(n >> 2) * 4096 + icol * 4 + d] = v0;
                        out[(size_t)(n >> 2) * 4096 + (icol + 1) * 4 + d] = v1;
                    } else {
                        __half h0 = __float2half(v0), h1 = __float2half(v1);
                        __half2 hh; hh.x = h0; hh.y = h1;
                        *(__half2*)(Voh + (size_t)n * 1024 + icol) = hh;
                        __half2 ll;
                        ll.x = __float2half(v0 - __half2float(h0));
                        ll.y = __float2half(v1 - __half2float(h1));
                        *(__half2*)(Vol + (size_t)n * 1024 + icol) = ll;
                    }
                }
            }
        }
    }
}

// ---------------------------------------------------------------------------
// Launch
// ---------------------------------------------------------------------------
extern "C" void kernel_launch(void* const* d_in, const int* in_sizes, int n_in,
                              void* d_out, int out_size) {
    const float* x     = (const float*)d_in[0];   // [B, IN]
    const float* W_in  = (const float*)d_in[1];   // [IN, OUT, D]
    const float* omega = (const float*)d_in[2];   // [OUT, D]
    const float* coup  = (const float*)d_in[3];   // [OUT, OUT]
    float* out = (float*)d_out;                   // [B, OUT, D]

    cudaFuncSetAttribute(gemm_f16<0>, cudaFuncAttributeMaxDynamicSharedMemorySize, DSMEM);
    cudaFuncSetAttribute(gemm_f16<1>, cudaFuncAttributeMaxDynamicSharedMemorySize, DSMEM);
    cudaFuncSetAttribute(gemm_f16<2>, cudaFuncAttributeMaxDynamicSharedMemorySize, DSMEM);

    prep_kt<<<(OUT_SZ * OUT_SZ) / 256, 256>>>(coup);
    prep_x<<<(B_SZ * IN_SZ) / 256, 256>>>(x);
    prep_wt<<<dim3(MTOT_I / 32, IN_SZ / 32), 256>>>(W_in);

    // init: M = 4096 (m=(o,d)), N = 8192 (b)
    gemm_f16<0><<<dim3(B_SZ / BTN, MTOT_I / BTM), NTHR, DSMEM>>>(0, omega, out);

    // steps: M = 32768 (n rows), N = 1024 (i); x-dim (i blocks) fastest -> A-tile L2 reuse
    dim3 sgrid(OUT_SZ / BTN, NROW / BTM);
    int s = 0;
    for (int t = 0; t < NSTEPS - 1; t++) {
        gemm_f16<1><<<sgrid, NTHR, DSMEM>>>(s, omega, out);
        s ^= 1;
    }
    gemm_f16<2><<<sgrid, NTHR, DSMEM>>>(s, omega, out);
}

// round 16
// speedup vs baseline: 1.0040x; 1.0040x over previous
#include <cuda_runtime.h>
#include <cuda_fp16.h>
#include <math.h>
#include <stdint.h>

// ---------------- problem constants ----------------
#define B_SZ   8192
#define OUT_SZ 1024
#define IN_SZ  1024
#define D_SZ   4
#define NSTEPS 8
#define NROW   (B_SZ * D_SZ)          /* 32768 state rows n = b*4+d */
#define MTOT_I (OUT_SZ * D_SZ)        /* 4096 init-GEMM M */
#define EPS_N  1e-12f

// ---------------- tiling ----------------
#define BTM  128                      /* CTA tile M */
#define BTN  256                      /* CTA tile N */
#define KCH  64                       /* k per chunk */
#define NCHUNK 16                     /* K = 1024 */
#define NTHR 512                      /* 16 warps: 4 (m) x 4 (n), warp tile 32x64 */
#define STAGES 2
// stage layout: Ah 16KB | Al 16KB | Bh 32KB | Bl 32KB = 96KB
#define A_LO_OFF 16384
#define B_OFF    32768
#define B_SUB    32768
#define STG_BYTES 98304
#define DSMEM (STAGES * STG_BYTES + 1024)

#define SWZ(o) ((o) ^ (((o) >> 3) & 0x70))

// ---------------- device buffers (split fp16) ----------------
__device__ __half g_Kth[OUT_SZ * OUT_SZ];               // tanh(coupling)+I, [i][j]
__device__ __half g_Ktl[OUT_SZ * OUT_SZ];
__device__ __half g_Wth[(size_t)MTOT_I * IN_SZ];        // W transposed [m=(o,d)][k]
__device__ __half g_Wtl[(size_t)MTOT_I * IN_SZ];
__device__ __half g_xh[(size_t)B_SZ * IN_SZ];           // x [b][k]
__device__ __half g_xl[(size_t)B_SZ * IN_SZ];
__device__ __half g_Vh[2][(size_t)NROW * OUT_SZ];       // state [n][j]
__device__ __half g_Vl[2][(size_t)NROW * OUT_SZ];

// ---------------- PTX helpers (baseline, sm_80-era) ----------------
__device__ __forceinline__ uint32_t smem_u32(const void* p) {
    uint32_t a;
    asm("{ .reg .u64 t; cvta.to.shared.u64 t, %1; cvt.u32.u64 %0, t; }" : "=r"(a) : "l"(p));
    return a;
}
__device__ __forceinline__ void cpasync16(uint32_t dst, const void* src) {
    asm volatile("cp.async.cg.shared.global [%0], [%1], 16;" :: "r"(dst), "l"(src));
}
#define CP_COMMIT() asm volatile("cp.async.commit_group;" ::: "memory")
#define CP_WAIT1()  asm volatile("cp.async.wait_group 1;" ::: "memory")

__device__ __forceinline__ void ldsm4(uint32_t* r, uint32_t addr) {
    asm volatile("ldmatrix.sync.aligned.m8n8.x4.shared.b16 {%0,%1,%2,%3}, [%4];"
                 : "=r"(r[0]), "=r"(r[1]), "=r"(r[2]), "=r"(r[3]) : "r"(addr));
}
// fp32-accumulate MMA (main pass)
__device__ __forceinline__ void mma16816(float* d, const uint32_t* a, const uint32_t* b) {
    asm volatile(
        "mma.sync.aligned.m16n8k16.row.col.f32.f16.f16.f32 "
        "{%0,%1,%2,%3}, {%4,%5,%6,%7}, {%8,%9}, {%0,%1,%2,%3};"
        : "+f"(d[0]), "+f"(d[1]), "+f"(d[2]), "+f"(d[3])
        : "r"(a[0]), "r"(a[1]), "r"(a[2]), "r"(a[3]), "r"(b[0]), "r"(b[1]));
}
// fp16-accumulate MMA (correction passes; values ~2^-11 scale, no overflow)
__device__ __forceinline__ void mma16816h(uint32_t* d, const uint32_t* a, const uint32_t* b) {
    asm volatile(
        "mma.sync.aligned.m16n8k16.row.col.f16.f16.f16.f16 "
        "{%0,%1}, {%2,%3,%4,%5}, {%6,%7}, {%0,%1};"
        : "+r"(d[0]), "+r"(d[1])
        : "r"(a[0]), "r"(a[1]), "r"(a[2]), "r"(a[3]), "r"(b[0]), "r"(b[1]));
}

// ---------------------------------------------------------------------------
// Prep kernels: build split-fp16 operands.
// ---------------------------------------------------------------------------
__global__ void prep_kt(const float* __restrict__ coup) {
    int idx = blockIdx.x * 256 + threadIdx.x;
    int i = idx >> 10, j = idx & 1023;
    float t = tanhf(coup[idx]) + (i == j ? 1.0f : 0.0f);
    __half h = __float2half(t);
    g_Kth[idx] = h;
    g_Ktl[idx] = __float2half(t - __half2float(h));
}

__global__ void prep_x(const float* __restrict__ x) {
    size_t idx = (size_t)blockIdx.x * 256 + threadIdx.x;
    float v = x[idx];
    __half h = __float2half(v);
    g_xh[idx] = h;
    g_xl[idx] = __float2half(v - __half2float(h));
}

// W[k][m] (1024 x 4096 row-major) -> Wt[m][k] split
__global__ void prep_wt(const float* __restrict__ W) {
    __shared__ float t[32][33];
    int tx = threadIdx.x & 31, ty = threadIdx.x >> 5;   // ty 0..7
    int m0 = blockIdx.x * 32, k0 = blockIdx.y * 32;
#pragma unroll
    for (int i = 0; i < 32; i += 8)
        t[ty + i][tx] = W[(size_t)(k0 + ty + i) * MTOT_I + m0 + tx];
    __syncthreads();
#pragma unroll
    for (int i = 0; i < 32; i += 8) {
        float v = t[tx][ty + i];
        __half h = __float2half(v);
        size_t off = (size_t)(m0 + ty + i) * IN_SZ + k0 + tx;
        g_Wth[off] = h;
        g_Wtl[off] = __float2half(v - __half2float(h));
    }
}

// ---------------------------------------------------------------------------
// Fused split-fp16 GEMM + normalize epilogue.
// C[m][n] = sum_k A[m][k]*B[n][k]
// pass1 (fp32 acc): ah*bh ; passes 2+3 (shared fp16 acc): ah*bl + al*bh
// MODE 0: init   A=Wt[m=(o,d)][k], B=x[b][k];  write V0[(b*4+d)][o] (norm over m-quads)
// MODE 1: step   A=Vt[n][j],       B=K'[i][j]; write Vout[n][i]     (norm over n-quads)
// MODE 2: step final -> write d_out[b][i][d] fp32
// ---------------------------------------------------------------------------
template <int MODE>
__global__ __launch_bounds__(NTHR, 1)
void gemm_f16(int sIn, const float* __restrict__ omega, float* __restrict__ out) {
    extern __shared__ char dsm_raw[];
    char* dsm = (char*)(((uintptr_t)dsm_raw + 1023) & ~(uintptr_t)1023);
    const uint32_t smemBase = smem_u32(dsm);

    const __half* __restrict__ Ah;
    const __half* __restrict__ Al;
    const __half* __restrict__ Bh;
    const __half* __restrict__ Bl;
    __half* __restrict__ Voh;
    __half* __restrict__ Vol;
    if (MODE == 0) {
        Ah = g_Wth; Al = g_Wtl; Bh = g_xh; Bl = g_xl;
        Voh = g_Vh[0]; Vol = g_Vl[0];
    } else {
        Ah = g_Vh[sIn]; Al = g_Vl[sIn]; Bh = g_Kth; Bl = g_Ktl;
        Voh = g_Vh[sIn ^ 1]; Vol = g_Vl[sIn ^ 1];
    }

    const int tid = threadIdx.x;
    const int lane = tid & 31;
    const int w = tid >> 5;
    const int wm = w & 3;        // 4 m-warps of 32 rows
    const int wn = w >> 2;       // 4 n-warps of 64 cols
    const int m0 = blockIdx.y * BTM;
    const int n0 = blockIdx.x * BTN;

    // ldmatrix per-thread UNSWIZZLED base offsets; swizzle applied per access.
    uint32_t aBase[2], bBase[4];
#pragma unroll
    for (int mi = 0; mi < 2; mi++) {
        int r = wm * 32 + mi * 16 + (lane & 7) + ((lane >> 3) & 1) * 8;
        int cc = (lane >> 4);
        aBase[mi] = (uint32_t)(r * 128 + cc * 16);
    }
#pragma unroll
    for (int nj = 0; nj < 4; nj++) {
        int r = wn * 64 + nj * 16 + (lane & 7) + ((lane >> 4) << 3);
        int cc = (lane >> 3) & 1;
        bBase[nj] = (uint32_t)(r * 128 + cc * 16);
    }

    float acc[2][8][4];
    uint32_t acch[2][8][2];      // fp16x2 accumulators for correction passes
#pragma unroll
    for (int a = 0; a < 2; a++)
#pragma unroll
        for (int b = 0; b < 8; b++) {
#pragma unroll
            for (int c = 0; c < 4; c++) acc[a][b][c] = 0.f;
            acch[a][b][0] = 0u; acch[a][b][1] = 0u;
        }

    // chunk copy (KCH=64): sub-tiles Ah|Al (16KB each), Bh|Bl (32KB each).
    auto copy_chunk = [&](int stage, int k0) {
        const uint32_t sb = smemBase + (uint32_t)(stage * STG_BYTES);
#pragma unroll
        for (int i = 0; i < 4; i++) {
            int u = tid + i * NTHR;
            int sub = u >> 10;                 // 0 = hi, 1 = lo
            int r = (u & 1023) >> 3, cc = u & 7;
            const __half* src = (sub ? Al : Ah) +
                (size_t)(m0 + r) * 1024 + k0 + cc * 8;
            cpasync16(sb + sub * A_LO_OFF + SWZ((uint32_t)(r * 128 + cc * 16)), src);
        }
#pragma unroll
        for (int i = 0; i < 8; i++) {
            int u = tid + i * NTHR;
            int sub = u >> 11;
            int r = (u & 2047) >> 3, cc = u & 7;
            const __half* src = (sub ? Bl : Bh) +
                (size_t)(n0 + r) * 1024 + k0 + cc * 8;
            cpasync16(sb + B_OFF + sub * B_SUB + SWZ((uint32_t)(r * 128 + cc * 16)), src);
        }
    };

    copy_chunk(0, 0);  CP_COMMIT();
    copy_chunk(1, KCH); CP_COMMIT();

    for (int c = 0; c < NCHUNK; c++) {
        CP_WAIT1();
        __syncthreads();
        const uint32_t stg = smemBase + (uint32_t)((c & 1) * STG_BYTES);

#pragma unroll
        for (int s = 0; s < 4; s++) {
            const uint32_t ks = (uint32_t)(s * 32);
            uint32_t ah[2][4], al[2][4];
#pragma unroll
            for (int mi = 0; mi < 2; mi++) {
                ldsm4(ah[mi], stg + SWZ(aBase[mi] + ks));
                ldsm4(al[mi], stg + A_LO_OFF + SWZ(aBase[mi] + ks));
            }
#pragma unroll
            for (int nj = 0; nj < 4; nj++) {
                uint32_t bh[4], bl[4];
                ldsm4(bh, stg + B_OFF + SWZ(bBase[nj] + ks));
                ldsm4(bl, stg + B_OFF + B_SUB + SWZ(bBase[nj] + ks));
#pragma unroll
                for (int mi = 0; mi < 2; mi++) {
                    // main pass: fp32 accumulate
                    mma16816(acc[mi][2 * nj + 0], ah[mi], &bh[0]);
                    mma16816(acc[mi][2 * nj + 1], ah[mi], &bh[2]);
                    // correction passes: shared fp16 accumulate
                    mma16816h(&acch[mi][2 * nj + 0][0], ah[mi], &bl[0]);
                    mma16816h(&acch[mi][2 * nj + 1][0], ah[mi], &bl[2]);
                    mma16816h(&acch[mi][2 * nj + 0][0], al[mi], &bh[0]);
                    mma16816h(&acch[mi][2 * nj + 1][0], al[mi], &bh[2]);
                }
            }
        }

        if (c + 2 < NCHUNK) {
            __syncthreads();               // all reads of this stage done
            copy_chunk(c & 1, (c + 2) * KCH);
        }
        CP_COMMIT();
    }

    // ---------------- epilogue (combine fp32 + fp16 accumulators) ----------------
    if (MODE == 0) {
        // rows m=(o,d), cols b. Normalize over m-quads: lanes {l, l^4, l^8}.
#pragma unroll
        for (int mi = 0; mi < 2; mi++) {
            const int mrow = m0 + wm * 32 + mi * 16 + (lane >> 2);
#pragma unroll
            for (int fi = 0; fi < 8; fi++) {
                const int bcol = n0 + wn * 64 + fi * 8 + (lane & 3) * 2;
                const __half2 c01 = *(__half2*)&acch[mi][fi][0];
                const __half2 c23 = *(__half2*)&acch[mi][fi][1];
#pragma unroll
                for (int h = 0; h < 2; h++) {
                    const int m = mrow + h * 8;
                    const int o = m >> 2, d = m & 3;
                    float v0 = acc[mi][fi][h * 2 + 0] +
                               __half2float(h ? c23.x : c01.x);
                    float v1 = acc[mi][fi][h * 2 + 1] +
                               __half2float(h ? c23.y : c01.y);
                    float s0 = v0 * v0, s1 = v1 * v1;
                    s0 += __shfl_xor_sync(~0u, s0, 4); s0 += __shfl_xor_sync(~0u, s0, 8);
                    s1 += __shfl_xor_sync(~0u, s1, 4); s1 += __shfl_xor_sync(~0u, s1, 8);
                    v0 *= 1.f / fmaxf(sqrtf(s0), EPS_N);
                    v1 *= 1.f / fmaxf(sqrtf(s1), EPS_N);
                    size_t p0 = (size_t)(bcol * 4 + d) * 1024 + o;
                    size_t p1 = (size_t)((bcol + 1) * 4 + d) * 1024 + o;
                    __half h0 = __float2half(v0), h1 = __float2half(v1);
                    Voh[p0] = h0; Vol[p0] = __float2half(v0 - __half2float(h0));
                    Voh[p1] = h1; Vol[p1] = __float2half(v1 - __half2float(h1));
                }
            }
        }
    } else {
        // rows n=(b,d), cols i. Normalize over n-quads: lanes {l, l^4, l^8}.
#pragma unroll
        for (int mi = 0; mi < 2; mi++) {
            const int nrow = m0 + wm * 32 + mi * 16 + (lane >> 2);
            const int d = nrow & 3;
#pragma unroll
            for (int fi = 0; fi < 8; fi++) {
                const int icol = n0 + wn * 64 + fi * 8 + (lane & 3) * 2;
                const float om0 = omega[icol * 4 + d];
                const float om1 = omega[icol * 4 + 4 + d];
                const __half2 c01 = *(__half2*)&acch[mi][fi][0];
                const __half2 c23 = *(__half2*)&acch[mi][fi][1];
#pragma unroll
                for (int h = 0; h < 2; h++) {
                    const int n = nrow + h * 8;
                    float v0 = acc[mi][fi][h * 2 + 0] +
                               __half2float(h ? c23.x : c01.x) + om0;
                    float v1 = acc[mi][fi][h * 2 + 1] +
                               __half2float(h ? c23.y : c01.y) + om1;
                    float s0 = v0 * v0, s1 = v1 * v1;
                    s0 += __shfl_xor_sync(~0u, s0, 4); s0 += __shfl_xor_sync(~0u, s0, 8);
                    s1 += __shfl_xor_sync(~0u, s1, 4); s1 += __shfl_xor_sync(~0u, s1, 8);
                    v0 *= 1.f / fmaxf(sqrtf(s0), EPS_N);
                    v1 *= 1.f / fmaxf(sqrtf(s1), EPS_N);
                    if (MODE == 2) {
                        out[(size_t)(n >> 2) * 4096 + icol * 4 + d] = v0;
                        out[(size_t)(n >> 2) * 4096 + (icol + 1) * 4 + d] = v1;
                    } else {
                        __half h0 = __float2half(v0), h1 = __float2half(v1);
                        __half2 hh; hh.x = h0; hh.y = h1;
                        *(__half2*)(Voh + (size_t)n * 1024 + icol) = hh;
                        __half2 ll;
                        ll.x = __float2half(v0 - __half2float(h0));
                        ll.y = __float2half(v1 - __half2float(h1));
                        *(__half2*)(Vol + (size_t)n * 1024 + icol) = ll;
                    }
                }
            }
        }
    }
}

// ---------------------------------------------------------------------------
// Launch
// ---------------------------------------------------------------------------
extern "C" void kernel_launch(void* const* d_in, const int* in_sizes, int n_in,
                              void* d_out, int out_size) {
    const float* x     = (const float*)d_in[0];   // [B, IN]
    const float* W_in  = (const float*)d_in[1];   // [IN, OUT, D]
    const float* omega = (const float*)d_in[2];   // [OUT, D]
    const float* coup  = (const float*)d_in[3];   // [OUT, OUT]
    float* out = (float*)d_out;                   // [B, OUT, D]

    cudaFuncSetAttribute(gemm_f16<0>, cudaFuncAttributeMaxDynamicSharedMemorySize, DSMEM);
    cudaFuncSetAttribute(gemm_f16<1>, cudaFuncAttributeMaxDynamicSharedMemorySize, DSMEM);
    cudaFuncSetAttribute(gemm_f16<2>, cudaFuncAttributeMaxDynamicSharedMemorySize, DSMEM);

    prep_kt<<<(OUT_SZ * OUT_SZ) / 256, 256>>>(coup);
    prep_x<<<(B_SZ * IN_SZ) / 256, 256>>>(x);
    prep_wt<<<dim3(MTOT_I / 32, IN_SZ / 32), 256>>>(W_in);

    // init: M = 4096 (m=(o,d)), N = 8192 (b)
    gemm_f16<0><<<dim3(B_SZ / BTN, MTOT_I / BTM), NTHR, DSMEM>>>(0, omega, out);

    // steps: M = 32768 (n rows), N = 1024 (i); x-dim (i blocks) fastest -> A-tile L2 reuse
    dim3 sgrid(OUT_SZ / BTN, NROW / BTM);
    int s = 0;
    for (int t = 0; t < NSTEPS - 1; t++) {
        gemm_f16<1><<<sgrid, NTHR, DSMEM>>>(s, omega, out);
        s ^= 1;
    }
    gemm_f16<2><<<sgrid, NTHR, DSMEM>>>(s, omega, out);
}